// round 6
// baseline (speedup 1.0000x reference)
#include <cuda_runtime.h>

// SparsifyAttention: attn [64,8,192,192] fp32.
// out[j] = exp(v_j - s) * sum_i [v_j >= t_i] * w_i / Z_i,
//   Z_i = sum_{v>=t_i} exp(v - s),  s = t1  (shift-invariant softmax).
// t_i = {96,128,144,153}-th largest per row.
//
// One warp per row, 6 vals/lane. 256-bin histogram over [-1.6, 0.8]
// (thresholds lie here with huge margin; edge bins clamp; the exact in-bin
// select handles any input). Z sums reduced via fixed-point REDUX.SUM
// (scale 2^14: bounded because exponents are shifted by t1).

#define FULLMASK 0xffffffffu

constexpr int   C     = 192;
constexpr int   VPT   = 6;
constexpr int   WARPS = 8;
constexpr int   NBINS = 256;
constexpr float BLO   = -1.6f;
constexpr float BSCALE = 256.0f / 2.4f;
constexpr float FPSCALE  = 16384.0f;        // 2^14
constexpr float IFPSCALE = 1.0f / 16384.0f;

__device__ __forceinline__ unsigned f2ord(float f) {
    unsigned u = __float_as_uint(f);
    unsigned m = (unsigned)(((int)u) >> 31) | 0x80000000u;
    return u ^ m;
}
__device__ __forceinline__ float ord2f(unsigned x) {
    unsigned m = (~(unsigned)(((int)x) >> 31)) | 0x80000000u;
    return __uint_as_float(x ^ m);
}

// k-th largest (1-based, multiset) of the warp's 192 values.
template <int K>
__device__ __forceinline__ float sel_kth(
    const int S[8], int suf, const float v[VPT], const int bin[VPT])
{
    const int above = suf - S[0];
    const int r0 = K - above;              // valid on the owning lane only
    int i = 0;
    #pragma unroll
    for (int j = 1; j < 8; j++) i += (S[j] >= r0);
    int sip1 = 0;                          // S[i+1] (S[8] = 0)
    #pragma unroll
    for (int j = 7; j >= 1; j--) sip1 = (S[j] >= r0) ? sip1 : S[j];
    int r = r0 - sip1;                     // rank within bin, from top

    const unsigned ball = __ballot_sync(FULLMASK, (suf >= K) && (above < K));
    const int L = __ffs(ball) - 1;
    const int b = 8 * L + __shfl_sync(FULLMASK, i, L);
    r = __shfl_sync(FULLMASK, r, L);

    // Fast path: bin max (exact when r == 1, the common case).
    float loc = -__int_as_float(0x7f800000);   // -inf
    #pragma unroll
    for (int j = 0; j < VPT; j++)
        if (bin[j] == b) loc = fmaxf(loc, v[j]);
    unsigned mx = __reduce_max_sync(FULLMASK, f2ord(loc));

    if (r > 1) {  // warp-uniform, rare
        int need = r;
        float bound = __int_as_float(0x7f800000);  // +inf
        while (true) {
            loc = -__int_as_float(0x7f800000);
            #pragma unroll
            for (int j = 0; j < VPT; j++)
                if (bin[j] == b && v[j] < bound) loc = fmaxf(loc, v[j]);
            mx = __reduce_max_sync(FULLMASK, f2ord(loc));
            const float fmx = ord2f(mx);
            int eq = 0;
            #pragma unroll
            for (int j = 0; j < VPT; j++)
                eq += (bin[j] == b) & (v[j] == fmx);
            need -= (int)__reduce_add_sync(FULLMASK, (unsigned)eq);
            if (need <= 0) break;
            bound = fmx;
        }
    }
    return ord2f(mx);
}

__global__ __launch_bounds__(32 * WARPS, 7)
void sparsify_attention_kernel(
    const float* __restrict__ attn,
    const float* __restrict__ w1p, const float* __restrict__ w2p,
    const float* __restrict__ w3p, const float* __restrict__ w4p,
    float* __restrict__ out, int nrows)
{
    __shared__ unsigned hist_s[WARPS][NBINS];

    const int lane = threadIdx.x & 31;
    const int wid  = threadIdx.x >> 5;
    const long long row = (long long)blockIdx.x * WARPS + wid;
    if (row >= nrows) return;

    unsigned* hist = hist_s[wid];

    // Zero histogram (two 128-bit stores per lane).
    const uint4 zz = make_uint4(0, 0, 0, 0);
    *reinterpret_cast<uint4*>(&hist[lane * 8])     = zz;
    *reinterpret_cast<uint4*>(&hist[lane * 8 + 4]) = zz;
    __syncwarp();

    // Vectorized row load.
    const float2* rp2 = reinterpret_cast<const float2*>(attn + row * (long long)C);
    float v[VPT];
    #pragma unroll
    for (int jj = 0; jj < 3; jj++) {
        float2 f = rp2[lane + 32 * jj];
        v[2 * jj]     = f.x;
        v[2 * jj + 1] = f.y;
    }

    // Bin + histogram.
    int bin[VPT];
    #pragma unroll
    for (int j = 0; j < VPT; j++) {
        int bi = (int)fminf(fmaxf((v[j] - BLO) * BSCALE, 0.0f), 255.0f);
        bin[j] = bi;
        atomicAdd(&hist[bi], 1u);
    }
    __syncwarp();

    // Chunk counts -> register suffix sums.
    const uint4 ca = *reinterpret_cast<const uint4*>(&hist[lane * 8]);
    const uint4 cb = *reinterpret_cast<const uint4*>(&hist[lane * 8 + 4]);
    int S[8];
    S[7] = (int)cb.w;
    S[6] = S[7] + (int)cb.z;
    S[5] = S[6] + (int)cb.y;
    S[4] = S[5] + (int)cb.x;
    S[3] = S[4] + (int)ca.w;
    S[2] = S[3] + (int)ca.z;
    S[1] = S[2] + (int)ca.y;
    S[0] = S[1] + (int)ca.x;

    // Inclusive suffix sum of chunk totals over lanes >= lane.
    int suf = S[0];
    #pragma unroll
    for (int d = 1; d < 32; d <<= 1) {
        int t = __shfl_down_sync(FULLMASK, suf, d);
        if (lane + d < 32) suf += t;
    }

    const float t1 = sel_kth< 96>(S, suf, v, bin);
    const float t2 = sel_kth<128>(S, suf, v, bin);
    const float t3 = sel_kth<144>(S, suf, v, bin);
    const float t4 = sel_kth<153>(S, suf, v, bin);

    // Fixed-point masked partition sums, reduced with REDUX.SUM.
    // Shift by t1: exponents v - t1 <= vmax - t1 (bounded, ~6), so
    // e <= ~400 and sums fit comfortably in uint32 at scale 2^14.
    unsigned zu1 = 0, zu2 = 0, zu3 = 0, zu4 = 0;
    #pragma unroll
    for (int j = 0; j < VPT; j++) {
        const float ex = __expf(v[j] - t1);
        const unsigned q = (unsigned)(ex * FPSCALE);
        if (v[j] >= t1) zu1 += q;
        if (v[j] >= t2) zu2 += q;
        if (v[j] >= t3) zu3 += q;
        if (v[j] >= t4) zu4 += q;
    }
    zu1 = __reduce_add_sync(FULLMASK, zu1);
    zu2 = __reduce_add_sync(FULLMASK, zu2);
    zu3 = __reduce_add_sync(FULLMASK, zu3);
    zu4 = __reduce_add_sync(FULLMASK, zu4);

    const float q1 = __fdividef(*w1p, (float)zu1 * IFPSCALE);
    const float q2 = __fdividef(*w2p, (float)zu2 * IFPSCALE);
    const float q3 = __fdividef(*w3p, (float)zu3 * IFPSCALE);
    const float q4 = __fdividef(*w4p, (float)zu4 * IFPSCALE);
    // Cumulative: passing t_i implies passing all lower thresholds.
    const float C4 = q4;
    const float C3 = C4 + q3;
    const float C2 = C3 + q2;
    const float C1 = C2 + q1;

    float2* op2 = reinterpret_cast<float2*>(out + row * (long long)C);
    #pragma unroll
    for (int jj = 0; jj < 3; jj++) {
        float2 o;
        #pragma unroll
        for (int h = 0; h < 2; h++) {
            const float vv = v[2 * jj + h];
            float c = 0.f;
            c = (vv >= t4) ? C4 : c;
            c = (vv >= t3) ? C3 : c;
            c = (vv >= t2) ? C2 : c;
            c = (vv >= t1) ? C1 : c;
            const float e = __expf(vv - t1);
            if (h == 0) o.x = e * c; else o.y = e * c;
        }
        op2[lane + 32 * jj] = o;
    }
}

extern "C" void kernel_launch(void* const* d_in, const int* in_sizes, int n_in,
                              void* d_out, int out_size)
{
    const float* attn = (const float*)d_in[0];
    const float* w1   = (const float*)d_in[1];
    const float* w2   = (const float*)d_in[2];
    const float* w3   = (const float*)d_in[3];
    const float* w4   = (const float*)d_in[4];
    float* out = (float*)d_out;

    const int nrows = in_sizes[0] / C;  // 98304
    const int blocks = (nrows + WARPS - 1) / WARPS;
    sparsify_attention_kernel<<<blocks, 32 * WARPS>>>(
        attn, w1, w2, w3, w4, out, nrows);
}

// round 8
// speedup vs baseline: 1.0795x; 1.0795x over previous
#include <cuda_runtime.h>

// SparsifyAttention: attn [64,8,192,192] fp32.
// out[j] = exp(v_j - t1) * sum_i [v_j >= t_i] * w_i / Z_i,
//   Z_i = sum_{v>=t_i} exp(v - t1)   (shift-invariant softmax).
// t_i = {96,128,144,153}-th largest per row.
//
// One warp per row, 6 vals/lane. 256-bin histogram over [-1.6, 0.8]
// (thresholds lie here with huge margin; edge bins clamp; exact in-bin
// select handles any input). Chunk suffix sums packed into bytes; per-k
// bin locate via SIMD byte compares. Z reduced by one REDUX.SUM each
// after a single float->fixed conversion (scale 2^14).

#define FULLMASK 0xffffffffu

constexpr int   C     = 192;
constexpr int   VPT   = 6;
constexpr int   WARPS = 8;
constexpr int   NBINS = 256;
constexpr float BLO   = -1.6f;
constexpr float BHI   = 0.8f;
constexpr float BINV  = 1.0f / (BHI - BLO);
constexpr float FPSCALE  = 16384.0f;        // 2^14
constexpr float IFPSCALE = 1.0f / 16384.0f;

__device__ __forceinline__ unsigned f2ord(float f) {
    unsigned u = __float_as_uint(f);
    unsigned m = (unsigned)(((int)u) >> 31) | 0x80000000u;
    return u ^ m;
}
__device__ __forceinline__ float ord2f(unsigned x) {
    unsigned m = (~(unsigned)(((int)x) >> 31)) | 0x80000000u;
    return __uint_as_float(x ^ m);
}

// k-th largest (1-based, multiset) of the warp's 192 values.
// S0: this lane's chunk total (bins [8L, 8L+8)). p0/p1: the 8 byte-packed
// suffix sums S[0..7] (S[i] = count in bins [8L+i, 8L+8)), S[i] <= 192.
// suf: inclusive suffix over lanes >= lane of S0.
template <int K>
__device__ __forceinline__ float sel_kth(
    int S0, unsigned p0, unsigned p1, int suf,
    const float v[VPT], const int bin[VPT])
{
    const int above = suf - S0;
    const int r0 = K - above;              // meaningful on the owning lane only
    const int r0c = max(1, min(255, r0));
    const unsigned splat = (unsigned)r0c * 0x01010101u;
    // i = (# of S[j] >= r0) - 1 : index of threshold bin within the chunk.
    const unsigned m0 = __vcmpgeu4(p0, splat);
    const unsigned m1 = __vcmpgeu4(p1, splat);
    const int i = ((__popc(m0) + __popc(m1)) >> 3) - 1;
    // S[i+1] (with S[8] = 0): count in bins above bin i within the chunk.
    const int sip1 = (i >= 7) ? 0 : (int)(__byte_perm(p0, p1, i + 1) & 0xFFu);
    const int r_local = r0 - sip1;         // 1-based rank within bin, from top

    const unsigned ball = __ballot_sync(FULLMASK, (suf >= K) && (above < K));
    const int L = __ffs(ball) - 1;
    const int b = 8 * L + __shfl_sync(FULLMASK, i, L);
    const int r = __shfl_sync(FULLMASK, r_local, L);

    // Fast path: bin max (exact when r == 1, the common case by bin design).
    float loc = -__int_as_float(0x7f800000);   // -inf
    #pragma unroll
    for (int j = 0; j < VPT; j++)
        if (bin[j] == b) loc = fmaxf(loc, v[j]);
    unsigned mx = __reduce_max_sync(FULLMASK, f2ord(loc));

    if (r > 1) {  // warp-uniform, rare: exact multiset select within bin b
        int need = r;
        float bound = __int_as_float(0x7f800000);  // +inf
        while (true) {
            loc = -__int_as_float(0x7f800000);
            #pragma unroll
            for (int j = 0; j < VPT; j++)
                if (bin[j] == b && v[j] < bound) loc = fmaxf(loc, v[j]);
            mx = __reduce_max_sync(FULLMASK, f2ord(loc));
            const float fmx = ord2f(mx);
            int eq = 0;
            #pragma unroll
            for (int j = 0; j < VPT; j++)
                eq += (bin[j] == b) & (v[j] == fmx);
            need -= (int)__reduce_add_sync(FULLMASK, (unsigned)eq);
            if (need <= 0) break;
            bound = fmx;
        }
    }
    return ord2f(mx);
}

__global__ __launch_bounds__(32 * WARPS, 6)
void sparsify_attention_kernel(
    const float* __restrict__ attn,
    const float* __restrict__ w1p, const float* __restrict__ w2p,
    const float* __restrict__ w3p, const float* __restrict__ w4p,
    float* __restrict__ out, int nrows)
{
    __shared__ unsigned hist_s[WARPS][NBINS];

    const int lane = threadIdx.x & 31;
    const int wid  = threadIdx.x >> 5;
    const long long row = (long long)blockIdx.x * WARPS + wid;
    if (row >= nrows) return;

    unsigned* hist = hist_s[wid];

    // Zero histogram (two 128-bit stores per lane).
    const uint4 zz = make_uint4(0, 0, 0, 0);
    *reinterpret_cast<uint4*>(&hist[lane * 8])     = zz;
    *reinterpret_cast<uint4*>(&hist[lane * 8 + 4]) = zz;
    __syncwarp();

    // Vectorized row load.
    const float2* rp2 = reinterpret_cast<const float2*>(attn + row * (long long)C);
    float v[VPT];
    #pragma unroll
    for (int jj = 0; jj < 3; jj++) {
        float2 f = rp2[lane + 32 * jj];
        v[2 * jj]     = f.x;
        v[2 * jj + 1] = f.y;
    }

    // Bin (FFMA.SAT + FMUL + F2I, clamp-free) + histogram.
    int bin[VPT];
    #pragma unroll
    for (int j = 0; j < VPT; j++) {
        const float f = __saturatef((v[j] - BLO) * BINV);
        const int bi = (int)(f * 255.0f);
        bin[j] = bi;
        atomicAdd(&hist[bi], 1u);
    }
    __syncwarp();

    // Chunk counts -> suffix sums, packed into bytes (S[i] <= 192 < 256).
    const uint4 ca = *reinterpret_cast<const uint4*>(&hist[lane * 8]);
    const uint4 cb = *reinterpret_cast<const uint4*>(&hist[lane * 8 + 4]);
    const int S7 = (int)cb.w;
    const int S6 = S7 + (int)cb.z;
    const int S5 = S6 + (int)cb.y;
    const int S4 = S5 + (int)cb.x;
    const int S3 = S4 + (int)ca.w;
    const int S2 = S3 + (int)ca.z;
    const int S1 = S2 + (int)ca.y;
    const int S0 = S1 + (int)ca.x;
    const unsigned p0 = (unsigned)S0 | ((unsigned)S1 << 8) |
                        ((unsigned)S2 << 16) | ((unsigned)S3 << 24);
    const unsigned p1 = (unsigned)S4 | ((unsigned)S5 << 8) |
                        ((unsigned)S6 << 16) | ((unsigned)S7 << 24);

    // Inclusive suffix sum of chunk totals over lanes >= lane.
    int suf = S0;
    #pragma unroll
    for (int d = 1; d < 32; d <<= 1) {
        int t = __shfl_down_sync(FULLMASK, suf, d);
        if (lane + d < 32) suf += t;
    }

    const float t1 = sel_kth< 96>(S0, p0, p1, suf, v, bin);
    const float t2 = sel_kth<128>(S0, p0, p1, suf, v, bin);
    const float t3 = sel_kth<144>(S0, p0, p1, suf, v, bin);
    const float t4 = sel_kth<153>(S0, p0, p1, suf, v, bin);

    // Float masked partition sums (fma pipe), one fixed-point convert per
    // accumulator, REDUX.SUM reduction. Exponents shifted by t1 keep every
    // term bounded (~e^6 max), so sums fit u32 at scale 2^14 with slack.
    float e[VPT];
    float z1 = 0.f, z2 = 0.f, z3 = 0.f, z4 = 0.f;
    #pragma unroll
    for (int j = 0; j < VPT; j++) {
        e[j] = __expf(v[j] - t1);
        z1 += (v[j] >= t1) ? e[j] : 0.f;
        z2 += (v[j] >= t2) ? e[j] : 0.f;
        z3 += (v[j] >= t3) ? e[j] : 0.f;
        z4 += (v[j] >= t4) ? e[j] : 0.f;
    }
    const unsigned zu1 = __reduce_add_sync(FULLMASK, (unsigned)(z1 * FPSCALE));
    const unsigned zu2 = __reduce_add_sync(FULLMASK, (unsigned)(z2 * FPSCALE));
    const unsigned zu3 = __reduce_add_sync(FULLMASK, (unsigned)(z3 * FPSCALE));
    const unsigned zu4 = __reduce_add_sync(FULLMASK, (unsigned)(z4 * FPSCALE));

    const float q1 = __fdividef(*w1p, (float)zu1 * IFPSCALE);
    const float q2 = __fdividef(*w2p, (float)zu2 * IFPSCALE);
    const float q3 = __fdividef(*w3p, (float)zu3 * IFPSCALE);
    const float q4 = __fdividef(*w4p, (float)zu4 * IFPSCALE);
    // Cumulative: passing t_i implies passing all lower thresholds.
    const float C4 = q4;
    const float C3 = C4 + q3;
    const float C2 = C3 + q2;
    const float C1 = C2 + q1;

    float2* op2 = reinterpret_cast<float2*>(out + row * (long long)C);
    #pragma unroll
    for (int jj = 0; jj < 3; jj++) {
        float2 o;
        #pragma unroll
        for (int h = 0; h < 2; h++) {
            const float vv = v[2 * jj + h];
            float c = 0.f;
            c = (vv >= t4) ? C4 : c;
            c = (vv >= t3) ? C3 : c;
            c = (vv >= t2) ? C2 : c;
            c = (vv >= t1) ? C1 : c;
            const float r = e[2 * jj + h] * c;
            if (h == 0) o.x = r; else o.y = r;
        }
        op2[lane + 32 * jj] = o;
    }
}

extern "C" void kernel_launch(void* const* d_in, const int* in_sizes, int n_in,
                              void* d_out, int out_size)
{
    const float* attn = (const float*)d_in[0];
    const float* w1   = (const float*)d_in[1];
    const float* w2   = (const float*)d_in[2];
    const float* w3   = (const float*)d_in[3];
    const float* w4   = (const float*)d_in[4];
    float* out = (float*)d_out;

    const int nrows = in_sizes[0] / C;  // 98304
    const int blocks = (nrows + WARPS - 1) / WARPS;
    sparsify_attention_kernel<<<blocks, 32 * WARPS>>>(
        attn, w1, w2, w3, w4, out, nrows);
}